// round 3
// baseline (speedup 1.0000x reference)
#include <cuda_runtime.h>
#include <cuda_bf16.h>
#include <math.h>

// Problem constants
#define S_LEN 1024
#define BATCH 4
#define DMODEL 1024
#define NHEAD 16
#define HDIM 64
#define M4 4096          // BATCH * S_LEN
#define DFF 4096
#define NREL 101         // 2*MAXREL+1
#define ASTRIDE 1152     // 1024 p + 101 bucket + 27 zero pad
#define KEXT 1125        // 1024 + 101

// ---------------- scratch (device globals; no allocations allowed) ----------
__device__ float g_hn  [M4 * DMODEL];          // rmsnorm(x) in [B,S,D] order
__device__ float g_q   [M4 * DMODEL];
__device__ float g_k   [M4 * DMODEL];
__device__ float g_v   [M4 * DMODEL];
__device__ float g_qrel[64 * 1024 * NREL];     // [bh, q, r]
__device__ float g_attn[75497472];             // [bh, q, ASTRIDE] = 64*1024*1152
__device__ float g_o   [M4 * DMODEL];          // attention head outputs [B,S,D]
__device__ float g_h2  [M4 * DMODEL];          // h + attn_out
__device__ float g_ffin[M4 * DMODEL];          // rmsnorm(h2)
__device__ float g_gelu[(size_t)M4 * DFF];     // gelu(ff @ W_in^T + b_in)

// ---------------- helpers ----------------------------------------------------
__device__ __forceinline__ float gelu_f(float x) {
    return 0.5f * x * (1.0f + erff(x * 0.70710678118654752f));
}

// 256-thread block reduce (8 warps). domax: true -> max, false -> sum.
__device__ __forceinline__ float blk_reduce(float v, float* red, bool domax) {
    #pragma unroll
    for (int o = 16; o > 0; o >>= 1) {
        float u = __shfl_xor_sync(0xffffffffu, v, o);
        v = domax ? fmaxf(v, u) : (v + u);
    }
    __syncthreads();
    if ((threadIdx.x & 31) == 0) red[threadIdx.x >> 5] = v;
    __syncthreads();
    float t = red[0];
    #pragma unroll
    for (int i = 1; i < 8; i++) t = domax ? fmaxf(t, red[i]) : (t + red[i]);
    return t;
}

// ---------------- RMSNorm -----------------------------------------------------
// transpose_in = 1: input rows are [s*B+b] (x layout), output rows [b*S+s].
__global__ void __launch_bounds__(256)
rmsnorm_kernel(const float* __restrict__ in, const float* __restrict__ g,
               float* __restrict__ out, int transpose_in) {
    __shared__ float red[8];
    int row = blockIdx.x;
    int tid = threadIdx.x;
    const float* xr = in + (size_t)row * DMODEL;
    float4 v = *(const float4*)&xr[tid * 4];
    float ss = v.x * v.x + v.y * v.y + v.z * v.z + v.w * v.w;
    ss = blk_reduce(ss, red, false);
    float rms = sqrtf(ss) * 0.03125f;                // /sqrt(1024)
    float inv = 1.0f / (rms + 1e-8f);
    float4 gv = *(const float4*)&g[tid * 4];
    float4 o = make_float4(v.x * inv * gv.x, v.y * inv * gv.y,
                           v.z * inv * gv.z, v.w * inv * gv.w);
    size_t orow = row;
    if (transpose_in) {
        int s = row >> 2, b = row & 3;               // row = s*B+b
        orow = ((size_t)b << 10) + s;                // out row = b*S+s
    }
    *(float4*)&out[orow * DMODEL + tid * 4] = o;
}

// ---------------- generic SGEMM: C[M,N] = A[M,K] @ W[N,K]^T  ------------------
// EPI: 0 = +bias ; 1 = +bias,gelu ; 2 = +bias,+res[m*1024+n] ;
//      3 = +bias,+res[m*1024+n], transposed write out[(s*B+b)*D + n]
// Assumes M%128==0, N%128==0, K%16==0.
template <int EPI>
__global__ void __launch_bounds__(256)
sgemm_kernel(const float* __restrict__ A, const float* __restrict__ W,
             const float* __restrict__ bias, const float* __restrict__ res,
             float* __restrict__ C, int M, int N, int K) {
    __shared__ float sA[16][132];
    __shared__ float sB[16][132];
    int tid = threadIdx.x;
    int m0 = blockIdx.y * 128;
    int n0 = blockIdx.x * 128;
    int tx = tid & 15, ty = tid >> 4;
    int lr = tid >> 2;              // 0..63
    int lc = (tid & 3) * 4;         // 0,4,8,12
    const float* Ag = A + (size_t)(m0 + lr) * K + lc;
    const float* Wg = W + (size_t)(n0 + lr) * K + lc;
    float acc[8][8] = {};
    for (int k0 = 0; k0 < K; k0 += 16) {
        float4 a0 = *(const float4*)Ag;
        float4 a1 = *(const float4*)(Ag + (size_t)64 * K);
        float4 b0 = *(const float4*)Wg;
        float4 b1 = *(const float4*)(Wg + (size_t)64 * K);
        Ag += 16; Wg += 16;
        sA[lc + 0][lr] = a0.x; sA[lc + 1][lr] = a0.y;
        sA[lc + 2][lr] = a0.z; sA[lc + 3][lr] = a0.w;
        sA[lc + 0][lr + 64] = a1.x; sA[lc + 1][lr + 64] = a1.y;
        sA[lc + 2][lr + 64] = a1.z; sA[lc + 3][lr + 64] = a1.w;
        sB[lc + 0][lr] = b0.x; sB[lc + 1][lr] = b0.y;
        sB[lc + 2][lr] = b0.z; sB[lc + 3][lr] = b0.w;
        sB[lc + 0][lr + 64] = b1.x; sB[lc + 1][lr + 64] = b1.y;
        sB[lc + 2][lr + 64] = b1.z; sB[lc + 3][lr + 64] = b1.w;
        __syncthreads();
        #pragma unroll
        for (int kk = 0; kk < 16; kk++) {
            float4 x0 = *(const float4*)&sA[kk][ty * 8];
            float4 x1 = *(const float4*)&sA[kk][ty * 8 + 4];
            float4 y0 = *(const float4*)&sB[kk][tx * 8];
            float4 y1 = *(const float4*)&sB[kk][tx * 8 + 4];
            float av[8] = {x0.x, x0.y, x0.z, x0.w, x1.x, x1.y, x1.z, x1.w};
            float bv[8] = {y0.x, y0.y, y0.z, y0.w, y1.x, y1.y, y1.z, y1.w};
            #pragma unroll
            for (int i = 0; i < 8; i++)
                #pragma unroll
                for (int j = 0; j < 8; j++)
                    acc[i][j] += av[i] * bv[j];
        }
        __syncthreads();
    }
    // epilogue
    int nbase = n0 + tx * 8;
    float4 bz0 = *(const float4*)&bias[nbase];
    float4 bz1 = *(const float4*)&bias[nbase + 4];
    float bb[8] = {bz0.x, bz0.y, bz0.z, bz0.w, bz1.x, bz1.y, bz1.z, bz1.w};
    #pragma unroll
    for (int i = 0; i < 8; i++) {
        int m = m0 + ty * 8 + i;
        float vals[8];
        #pragma unroll
        for (int j = 0; j < 8; j++) {
            float v = acc[i][j] + bb[j];
            if (EPI == 1) v = gelu_f(v);
            vals[j] = v;
        }
        if (EPI == 2 || EPI == 3) {
            float4 r0 = *(const float4*)&res[(size_t)m * 1024 + nbase];
            float4 r1 = *(const float4*)&res[(size_t)m * 1024 + nbase + 4];
            vals[0] += r0.x; vals[1] += r0.y; vals[2] += r0.z; vals[3] += r0.w;
            vals[4] += r1.x; vals[5] += r1.y; vals[6] += r1.z; vals[7] += r1.w;
        }
        size_t obase;
        if (EPI == 3) {
            int b = m >> 10, s = m & 1023;           // m = b*S+s
            obase = ((size_t)(s * BATCH + b)) * DMODEL + nbase;
        } else {
            obase = (size_t)m * N + nbase;
        }
        *(float4*)&C[obase]     = make_float4(vals[0], vals[1], vals[2], vals[3]);
        *(float4*)&C[obase + 4] = make_float4(vals[4], vals[5], vals[6], vals[7]);
    }
}

// ---------------- qrel: qrel[bh,q,r] = q_head[q,:] . rel_k[r,:] ---------------
__global__ void __launch_bounds__(256)
qrel_kernel(const float* __restrict__ q, const float* __restrict__ relk,
            float* __restrict__ qrel) {
    __shared__ float sR[NREL][65];
    __shared__ float sQ[64][65];
    int bh = blockIdx.y;
    int b = bh >> 4, h = bh & 15;
    int q0 = blockIdx.x * 64;
    int tid = threadIdx.x;
    const float* Q = q + ((size_t)(b * S_LEN) + q0) * DMODEL + h * HDIM;
    for (int i = tid; i < NREL * 64; i += 256) {
        int r = i >> 6, d = i & 63;
        sR[r][d] = relk[i];
    }
    for (int i = tid; i < 64 * 64; i += 256) {
        int r = i >> 6, d = i & 63;
        sQ[r][d] = Q[(size_t)r * DMODEL + d];
    }
    __syncthreads();
    for (int i = tid; i < 64 * NREL; i += 256) {
        int qq = i / NREL, r = i % NREL;
        float s = 0.f;
        #pragma unroll
        for (int d = 0; d < 64; d++) s += sQ[qq][d] * sR[r][d];
        qrel[((size_t)bh * 1024 + q0 + qq) * NREL + r] = s;
    }
}

// ---------------- scores: attn[bh,q,k] = (q.k + qrel[clip(k-q)]) / 8 ----------
__global__ void __launch_bounds__(256)
score_kernel(const float* __restrict__ q, const float* __restrict__ k,
             const float* __restrict__ qrel, float* __restrict__ attn) {
    __shared__ float sQ[64][65];
    __shared__ float sK[64][65];
    int bh = blockIdx.z;
    int b = bh >> 4, h = bh & 15;
    int q0 = blockIdx.y * 64, k0 = blockIdx.x * 64;
    int tid = threadIdx.x;
    const float* Q  = q + (size_t)(b * S_LEN) * DMODEL + h * HDIM;
    const float* Kp = k + (size_t)(b * S_LEN) * DMODEL + h * HDIM;
    #pragma unroll
    for (int it = 0; it < 4; it++) {
        int r = (tid >> 4) + it * 16;
        int c = (tid & 15) * 4;
        float4 v = *(const float4*)&Q[(size_t)(q0 + r) * DMODEL + c];
        sQ[r][c] = v.x; sQ[r][c + 1] = v.y; sQ[r][c + 2] = v.z; sQ[r][c + 3] = v.w;
        float4 w = *(const float4*)&Kp[(size_t)(k0 + r) * DMODEL + c];
        sK[r][c] = w.x; sK[r][c + 1] = w.y; sK[r][c + 2] = w.z; sK[r][c + 3] = w.w;
    }
    __syncthreads();
    int tx = tid & 15, ty = tid >> 4;
    float acc[4][4] = {};
    #pragma unroll
    for (int kk = 0; kk < 64; kk++) {
        float a[4], bb[4];
        #pragma unroll
        for (int i = 0; i < 4; i++) a[i] = sQ[ty * 4 + i][kk];
        #pragma unroll
        for (int j = 0; j < 4; j++) bb[j] = sK[tx * 4 + j][kk];
        #pragma unroll
        for (int i = 0; i < 4; i++)
            #pragma unroll
            for (int j = 0; j < 4; j++)
                acc[i][j] += a[i] * bb[j];
    }
    size_t rowbase = (size_t)bh * 1024;
    #pragma unroll
    for (int i = 0; i < 4; i++) {
        int qq = q0 + ty * 4 + i;
        const float* qr = qrel + (rowbase + qq) * NREL;
        float* out = attn + (rowbase + qq) * ASTRIDE;
        #pragma unroll
        for (int j = 0; j < 4; j++) {
            int kki = k0 + tx * 4 + j;
            int d = kki - qq;
            d = min(max(d, -50), 50);
            out[kki] = (acc[i][j] + qr[d + 50]) * 0.125f;
        }
    }
}

// ---------------- softmax + relative-position buckets ------------------------
__global__ void __launch_bounds__(256)
softmax_kernel(float* __restrict__ attn) {
    __shared__ float sp[1024];
    __shared__ float red[8];
    int row = blockIdx.x;               // bh*1024 + q
    int qq = row & 1023;
    float* p = attn + (size_t)row * ASTRIDE;
    int tid = threadIdx.x;
    float4 v = *(const float4*)&p[tid * 4];
    float m = fmaxf(fmaxf(v.x, v.y), fmaxf(v.z, v.w));
    m = blk_reduce(m, red, true);
    float e0 = expf(v.x - m), e1 = expf(v.y - m);
    float e2 = expf(v.z - m), e3 = expf(v.w - m);
    float s = blk_reduce(e0 + e1 + e2 + e3, red, false);
    float inv = 1.0f / s;
    e0 *= inv; e1 *= inv; e2 *= inv; e3 *= inv;
    *(float4*)&p[tid * 4] = make_float4(e0, e1, e2, e3);
    sp[tid * 4 + 0] = e0; sp[tid * 4 + 1] = e1;
    sp[tid * 4 + 2] = e2; sp[tid * 4 + 3] = e3;
    __syncthreads();
    int lo = qq - 50, hi = qq + 50;
    float s0 = 0.f, s100 = 0.f;
    for (int kk = tid; kk < 1024; kk += 256) {
        float pv = sp[kk];
        if (kk <= lo) s0 += pv;
        if (kk >= hi) s100 += pv;
    }
    s0 = blk_reduce(s0, red, false);
    s100 = blk_reduce(s100, red, false);
    if (tid == 0) { p[1024] = s0; p[1024 + 100] = s100; }
    if (tid >= 1 && tid < 100) {
        int kk = qq + tid - 50;
        p[1024 + tid] = (kk >= 0 && kk < 1024) ? sp[kk] : 0.0f;
    }
    if (tid >= 100 && tid < 127) p[1025 + tid] = 0.0f;  // zero pad 1125..1151
}

// ---------------- AV (K-extended with rel_v) ---------------------------------
// o[b,q,h*64+d] = sum_{k<1024} p[q,k]*v[k,d] + sum_r bucket[q,r]*rel_v[r,d]
__global__ void __launch_bounds__(256)
av_kernel(const float* __restrict__ attn, const float* __restrict__ v,
          const float* __restrict__ relv, float* __restrict__ o) {
    __shared__ float sA[16][132];
    __shared__ float sB[16][68];
    int bh = blockIdx.y;
    int b = bh >> 4, h = bh & 15;
    int q0 = blockIdx.x * 128;
    int tid = threadIdx.x;
    int tx = tid & 15, ty = tid >> 4;
    int lr = tid >> 2;
    int lc = (tid & 3) * 4;
    int br = tid >> 4;               // 0..15
    int bc = (tid & 15) * 4;         // 0..60
    const float* Arow = attn + ((size_t)bh * 1024 + q0) * ASTRIDE;
    float acc[8][4] = {};
    for (int kt = 0; kt < 71; kt++) {  // ceil(1125/16)=71; cols<=1135 zero-padded
        int kk0 = kt * 16;
        float4 a0 = *(const float4*)&Arow[(size_t)lr * ASTRIDE + kk0 + lc];
        float4 a1 = *(const float4*)&Arow[(size_t)(lr + 64) * ASTRIDE + kk0 + lc];
        int kk = kk0 + br;
        float4 bv;
        if (kk < 1024)
            bv = *(const float4*)&v[((size_t)(b * S_LEN) + kk) * DMODEL + h * HDIM + bc];
        else if (kk < KEXT)
            bv = *(const float4*)&relv[(size_t)(kk - 1024) * HDIM + bc];
        else
            bv = make_float4(0.f, 0.f, 0.f, 0.f);
        sA[lc + 0][lr] = a0.x; sA[lc + 1][lr] = a0.y;
        sA[lc + 2][lr] = a0.z; sA[lc + 3][lr] = a0.w;
        sA[lc + 0][lr + 64] = a1.x; sA[lc + 1][lr + 64] = a1.y;
        sA[lc + 2][lr + 64] = a1.z; sA[lc + 3][lr + 64] = a1.w;
        *(float4*)&sB[br][bc] = bv;
        __syncthreads();
        #pragma unroll
        for (int k2 = 0; k2 < 16; k2++) {
            float4 x0 = *(const float4*)&sA[k2][ty * 8];
            float4 x1 = *(const float4*)&sA[k2][ty * 8 + 4];
            float4 y  = *(const float4*)&sB[k2][tx * 4];
            float av[8] = {x0.x, x0.y, x0.z, x0.w, x1.x, x1.y, x1.z, x1.w};
            float bw[4] = {y.x, y.y, y.z, y.w};
            #pragma unroll
            for (int i = 0; i < 8; i++)
                #pragma unroll
                for (int j = 0; j < 4; j++)
                    acc[i][j] += av[i] * bw[j];
        }
        __syncthreads();
    }
    #pragma unroll
    for (int i = 0; i < 8; i++) {
        int qq = q0 + ty * 8 + i;
        float* op = o + ((size_t)(b * S_LEN) + qq) * DMODEL + h * HDIM + tx * 4;
        *(float4*)op = make_float4(acc[i][0], acc[i][1], acc[i][2], acc[i][3]);
    }
}

// ---------------- host launch -------------------------------------------------
extern "C" void kernel_launch(void* const* d_in, const int* in_sizes, int n_in,
                              void* d_out, int out_size) {
    const float* x     = (const float*)d_in[0];
    const float* Wq    = (const float*)d_in[1];
    const float* bq    = (const float*)d_in[2];
    const float* Wk    = (const float*)d_in[3];
    const float* bk    = (const float*)d_in[4];
    const float* Wv    = (const float*)d_in[5];
    const float* bv    = (const float*)d_in[6];
    const float* Wo    = (const float*)d_in[7];
    const float* bo    = (const float*)d_in[8];
    const float* rel_k = (const float*)d_in[9];
    const float* rel_v = (const float*)d_in[10];
    const float* ga    = (const float*)d_in[11];
    const float* gf    = (const float*)d_in[12];
    const float* W_in  = (const float*)d_in[13];
    const float* b_in  = (const float*)d_in[14];
    const float* W_out = (const float*)d_in[15];
    const float* b_out = (const float*)d_in[16];
    float* out = (float*)d_out;

    float *hn, *qb, *kb, *vb, *qr, *at, *ob, *h2, *ffin, *gel;
    cudaGetSymbolAddress((void**)&hn,   g_hn);
    cudaGetSymbolAddress((void**)&qb,   g_q);
    cudaGetSymbolAddress((void**)&kb,   g_k);
    cudaGetSymbolAddress((void**)&vb,   g_v);
    cudaGetSymbolAddress((void**)&qr,   g_qrel);
    cudaGetSymbolAddress((void**)&at,   g_attn);
    cudaGetSymbolAddress((void**)&ob,   g_o);
    cudaGetSymbolAddress((void**)&h2,   g_h2);
    cudaGetSymbolAddress((void**)&ffin, g_ffin);
    cudaGetSymbolAddress((void**)&gel,  g_gelu);

    // 1. h = rmsnorm(x, g_attn), transpose [S,B,D] -> [B,S,D]
    rmsnorm_kernel<<<M4, 256>>>(x, ga, hn, 1);
    // 2. q, k, v
    dim3 g1(DMODEL / 128, M4 / 128);
    sgemm_kernel<0><<<g1, 256>>>(hn, Wq, bq, nullptr, qb, M4, DMODEL, DMODEL);
    sgemm_kernel<0><<<g1, 256>>>(hn, Wk, bk, nullptr, kb, M4, DMODEL, DMODEL);
    sgemm_kernel<0><<<g1, 256>>>(hn, Wv, bv, nullptr, vb, M4, DMODEL, DMODEL);
    // 3. qrel
    qrel_kernel<<<dim3(16, 64), 256>>>(qb, rel_k, qr);
    // 4. scores
    score_kernel<<<dim3(16, 16, 64), 256>>>(qb, kb, qr, at);
    // 5. softmax + buckets
    softmax_kernel<<<65536, 256>>>(at);
    // 6. AV (with rel_v K-extension)
    av_kernel<<<dim3(8, 64), 256>>>(at, vb, rel_v, ob);
    // 7. h2 = hn + o @ Wo^T + bo
    sgemm_kernel<2><<<g1, 256>>>(ob, Wo, bo, hn, h2, M4, DMODEL, DMODEL);
    // 8. ffin = rmsnorm(h2, g_ff)
    rmsnorm_kernel<<<M4, 256>>>(h2, gf, ffin, 0);
    // 9. gelu(ffin @ W_in^T + b_in)
    sgemm_kernel<1><<<dim3(DFF / 128, M4 / 128), 256>>>(ffin, W_in, b_in, nullptr,
                                                        gel, M4, DFF, DMODEL);
    // 10. out = h2 + gel @ W_out^T + b_out  (written back in [S,B,D] order)
    sgemm_kernel<3><<<g1, 256>>>(gel, W_out, b_out, h2, out, M4, DMODEL, DFF);
}

// round 4
// speedup vs baseline: 1.6230x; 1.6230x over previous
#include <cuda_runtime.h>
#include <cuda_bf16.h>
#include <math.h>
#include <stdint.h>

// Problem constants
#define S_LEN 1024
#define BATCH 4
#define DMODEL 1024
#define NHEAD 16
#define HDIM 64
#define M4 4096          // BATCH * S_LEN
#define DFF 4096
#define NREL 101         // 2*MAXREL+1
#define ASTRIDE 1152     // 1024 p + 101 bucket + 27 zero pad
#define KEXT 1125        // 1024 + 101

// ---------------- scratch (device globals; no allocations allowed) ----------
__device__ float g_hn  [M4 * DMODEL];          // rmsnorm(x) in [B,S,D] order
__device__ float g_q   [M4 * DMODEL];
__device__ float g_k   [M4 * DMODEL];
__device__ float g_v   [M4 * DMODEL];
__device__ float g_qrel[64 * 1024 * NREL];     // [bh, q, r]
__device__ float g_attn[75497472];             // [bh, q, ASTRIDE] = 64*1024*1152
__device__ float g_o   [M4 * DMODEL];          // attention head outputs [B,S,D]
__device__ float g_h2  [M4 * DMODEL];          // h + attn_out
__device__ float g_ffin[M4 * DMODEL];          // rmsnorm(h2)
__device__ float g_gelu[(size_t)M4 * DFF];     // gelu(ff @ W_in^T + b_in)

// ---------------- helpers ----------------------------------------------------
__device__ __forceinline__ float gelu_f(float x) {
    return 0.5f * x * (1.0f + erff(x * 0.70710678118654752f));
}

__device__ __forceinline__ uint32_t f2tf(float f) {
    uint32_t u;
    asm("cvt.rna.tf32.f32 %0, %1;" : "=r"(u) : "f"(f));
    return u;
}

// D = A(16x8, row) * B(8x8, col) + D   (tf32 inputs, f32 accum)
__device__ __forceinline__ void mma8(float* c, const uint32_t* a, const uint32_t* b) {
    asm volatile(
        "mma.sync.aligned.m16n8k8.row.col.f32.tf32.tf32.f32 "
        "{%0,%1,%2,%3}, {%4,%5,%6,%7}, {%8,%9}, {%0,%1,%2,%3};"
        : "+f"(c[0]), "+f"(c[1]), "+f"(c[2]), "+f"(c[3])
        : "r"(a[0]), "r"(a[1]), "r"(a[2]), "r"(a[3]), "r"(b[0]), "r"(b[1]));
}

// 256-thread block reduce (8 warps). domax: true -> max, false -> sum.
__device__ __forceinline__ float blk_reduce(float v, float* red, bool domax) {
    #pragma unroll
    for (int o = 16; o > 0; o >>= 1) {
        float u = __shfl_xor_sync(0xffffffffu, v, o);
        v = domax ? fmaxf(v, u) : (v + u);
    }
    __syncthreads();
    if ((threadIdx.x & 31) == 0) red[threadIdx.x >> 5] = v;
    __syncthreads();
    float t = red[0];
    #pragma unroll
    for (int i = 1; i < 8; i++) t = domax ? fmaxf(t, red[i]) : (t + red[i]);
    return t;
}

// ---------------- RMSNorm -----------------------------------------------------
__global__ void __launch_bounds__(256)
rmsnorm_kernel(const float* __restrict__ in, const float* __restrict__ g,
               float* __restrict__ out, int transpose_in) {
    __shared__ float red[8];
    int row = blockIdx.x;
    int tid = threadIdx.x;
    const float* xr = in + (size_t)row * DMODEL;
    float4 v = *(const float4*)&xr[tid * 4];
    float ss = v.x * v.x + v.y * v.y + v.z * v.z + v.w * v.w;
    ss = blk_reduce(ss, red, false);
    float rms = sqrtf(ss) * 0.03125f;                // /sqrt(1024)
    float inv = 1.0f / (rms + 1e-8f);
    float4 gv = *(const float4*)&g[tid * 4];
    float4 o = make_float4(v.x * inv * gv.x, v.y * inv * gv.y,
                           v.z * inv * gv.z, v.w * inv * gv.w);
    size_t orow = row;
    if (transpose_in) {
        int s = row >> 2, b = row & 3;               // row = s*B+b
        orow = ((size_t)b << 10) + s;                // out row = b*S+s
    }
    *(float4*)&out[orow * DMODEL + tid * 4] = o;
}

// ---------------- tf32 tensor-core GEMM: C[M,N] = A[M,K] @ W[N,K]^T -----------
// EPI: 0 = +bias ; 1 = +bias,gelu ; 2 = +bias,+res[m*1024+n] ;
//      3 = +bias,+res[m*1024+n], transposed write out[(s*B+b)*D + n]
// M%128==0, N%128==0, K%32==0. 256 threads, 8 warps as 2(m) x 4(n),
// warp tile 64x32 via m16n8k8 subtiles.
template <int EPI>
__global__ void __launch_bounds__(256)
tgemm_kernel(const float* __restrict__ A, const float* __restrict__ W,
             const float* __restrict__ bias, const float* __restrict__ res,
             float* __restrict__ C, int M, int N, int K) {
    __shared__ uint32_t sA[32][132];
    __shared__ uint32_t sB[32][132];
    int tid = threadIdx.x;
    int m0 = blockIdx.y * 128, n0 = blockIdx.x * 128;
    int warp = tid >> 5, lane = tid & 31;
    int wm = (warp & 1) * 64, wn = (warp >> 1) * 32;
    int r = lane >> 2, cq = lane & 3;
    int lrow = tid >> 1, lcg = (tid & 1) * 16;
    const float* Ag = A + (size_t)(m0 + lrow) * K + lcg;
    const float* Wg = W + (size_t)(n0 + lrow) * K + lcg;
    float acc[4][4][4] = {};
    for (int k0 = 0; k0 < K; k0 += 32) {
        #pragma unroll
        for (int it = 0; it < 4; it++) {
            float4 va = *(const float4*)(Ag + k0 + it * 4);
            float4 vb = *(const float4*)(Wg + k0 + it * 4);
            int kc = lcg + it * 4;
            sA[kc + 0][lrow] = f2tf(va.x); sA[kc + 1][lrow] = f2tf(va.y);
            sA[kc + 2][lrow] = f2tf(va.z); sA[kc + 3][lrow] = f2tf(va.w);
            sB[kc + 0][lrow] = f2tf(vb.x); sB[kc + 1][lrow] = f2tf(vb.y);
            sB[kc + 2][lrow] = f2tf(vb.z); sB[kc + 3][lrow] = f2tf(vb.w);
        }
        __syncthreads();
        #pragma unroll
        for (int kk = 0; kk < 32; kk += 8) {
            uint32_t af[4][4], bf[4][2];
            #pragma unroll
            for (int i = 0; i < 4; i++) {
                int mi = wm + i * 16 + r;
                af[i][0] = sA[kk + cq][mi];     af[i][1] = sA[kk + cq][mi + 8];
                af[i][2] = sA[kk + cq + 4][mi]; af[i][3] = sA[kk + cq + 4][mi + 8];
            }
            #pragma unroll
            for (int j = 0; j < 4; j++) {
                int nj = wn + j * 8 + r;
                bf[j][0] = sB[kk + cq][nj];
                bf[j][1] = sB[kk + cq + 4][nj];
            }
            #pragma unroll
            for (int i = 0; i < 4; i++)
                #pragma unroll
                for (int j = 0; j < 4; j++)
                    mma8(acc[i][j], af[i], bf[j]);
        }
        __syncthreads();
    }
    // epilogue
    float2 bb[4];
    #pragma unroll
    for (int j = 0; j < 4; j++)
        bb[j] = *(const float2*)&bias[n0 + wn + j * 8 + 2 * cq];
    #pragma unroll
    for (int i = 0; i < 4; i++)
        #pragma unroll
        for (int ph = 0; ph < 2; ph++) {
            int m = m0 + wm + i * 16 + r + ph * 8;
            #pragma unroll
            for (int j = 0; j < 4; j++) {
                int col = n0 + wn + j * 8 + 2 * cq;
                float v0 = acc[i][j][ph * 2 + 0] + bb[j].x;
                float v1 = acc[i][j][ph * 2 + 1] + bb[j].y;
                if (EPI == 1) { v0 = gelu_f(v0); v1 = gelu_f(v1); }
                if (EPI == 2 || EPI == 3) {
                    float2 rr = *(const float2*)&res[(size_t)m * 1024 + col];
                    v0 += rr.x; v1 += rr.y;
                }
                size_t ob;
                if (EPI == 3) {
                    int b = m >> 10, s = m & 1023;
                    ob = ((size_t)(s * BATCH + b)) * DMODEL + col;
                } else {
                    ob = (size_t)m * N + col;
                }
                *(float2*)&C[ob] = make_float2(v0, v1);
            }
        }
}

// ---------------- qrel: qrel[bh,q,r] = q_head[q,:] . rel_k[r,:] ---------------
__global__ void __launch_bounds__(256)
qrel_kernel(const float* __restrict__ q, const float* __restrict__ relk,
            float* __restrict__ qrel) {
    __shared__ float sR[NREL][65];
    __shared__ float sQ[64][65];
    int bh = blockIdx.y;
    int b = bh >> 4, h = bh & 15;
    int q0 = blockIdx.x * 64;
    int tid = threadIdx.x;
    const float* Q = q + ((size_t)(b * S_LEN) + q0) * DMODEL + h * HDIM;
    for (int i = tid; i < NREL * 64; i += 256) {
        int r = i >> 6, d = i & 63;
        sR[r][d] = relk[i];
    }
    for (int i = tid; i < 64 * 64; i += 256) {
        int r = i >> 6, d = i & 63;
        sQ[r][d] = Q[(size_t)r * DMODEL + d];
    }
    __syncthreads();
    for (int i = tid; i < 64 * NREL; i += 256) {
        int qq = i / NREL, r = i % NREL;
        float s = 0.f;
        #pragma unroll
        for (int d = 0; d < 64; d++) s += sQ[qq][d] * sR[r][d];
        qrel[((size_t)bh * 1024 + q0 + qq) * NREL + r] = s;
    }
}

// ---------------- scores: attn[bh,q,k] = (q.k + qrel[clip(k-q)]) / 8 ----------
// tf32 mma version: 64x64 tile, K=64. 8 warps as 2(m) x 4(n), warp 32x16.
__global__ void __launch_bounds__(256)
score_kernel(const float* __restrict__ q, const float* __restrict__ k,
             const float* __restrict__ qrel, float* __restrict__ attn) {
    __shared__ uint32_t sQ[64][68];
    __shared__ uint32_t sK[64][68];
    int bh = blockIdx.z;
    int b = bh >> 4, hd = bh & 15;
    int q0 = blockIdx.y * 64, k0 = blockIdx.x * 64;
    int tid = threadIdx.x;
    const float* Q  = q + ((size_t)(b * S_LEN) + q0) * DMODEL + hd * HDIM;
    const float* Kp = k + ((size_t)(b * S_LEN) + k0) * DMODEL + hd * HDIM;
    int lrow = tid >> 2, lcg = (tid & 3) * 16;
    #pragma unroll
    for (int it = 0; it < 4; it++) {
        int c = lcg + it * 4;
        float4 v = *(const float4*)&Q[(size_t)lrow * DMODEL + c];
        sQ[c + 0][lrow] = f2tf(v.x); sQ[c + 1][lrow] = f2tf(v.y);
        sQ[c + 2][lrow] = f2tf(v.z); sQ[c + 3][lrow] = f2tf(v.w);
        float4 w = *(const float4*)&Kp[(size_t)lrow * DMODEL + c];
        sK[c + 0][lrow] = f2tf(w.x); sK[c + 1][lrow] = f2tf(w.y);
        sK[c + 2][lrow] = f2tf(w.z); sK[c + 3][lrow] = f2tf(w.w);
    }
    __syncthreads();
    int warp = tid >> 5, lane = tid & 31;
    int wm = (warp & 1) * 32, wn = (warp >> 1) * 16;
    int r = lane >> 2, cq = lane & 3;
    float acc[2][2][4] = {};
    #pragma unroll
    for (int kk = 0; kk < 64; kk += 8) {
        uint32_t af[2][4], bf[2][2];
        #pragma unroll
        for (int i = 0; i < 2; i++) {
            int mi = wm + i * 16 + r;
            af[i][0] = sQ[kk + cq][mi];     af[i][1] = sQ[kk + cq][mi + 8];
            af[i][2] = sQ[kk + cq + 4][mi]; af[i][3] = sQ[kk + cq + 4][mi + 8];
        }
        #pragma unroll
        for (int j = 0; j < 2; j++) {
            int nj = wn + j * 8 + r;
            bf[j][0] = sK[kk + cq][nj];
            bf[j][1] = sK[kk + cq + 4][nj];
        }
        #pragma unroll
        for (int i = 0; i < 2; i++)
            #pragma unroll
            for (int j = 0; j < 2; j++)
                mma8(acc[i][j], af[i], bf[j]);
    }
    size_t rowbase = (size_t)bh * 1024;
    #pragma unroll
    for (int i = 0; i < 2; i++)
        #pragma unroll
        for (int ph = 0; ph < 2; ph++) {
            int qq = q0 + wm + i * 16 + r + ph * 8;
            const float* qr = qrel + (rowbase + qq) * NREL;
            float* outr = attn + (rowbase + qq) * ASTRIDE;
            #pragma unroll
            for (int j = 0; j < 2; j++) {
                int kki = k0 + wn + j * 8 + 2 * cq;
                int d0 = min(max(kki - qq, -50), 50);
                int d1 = min(max(kki + 1 - qq, -50), 50);
                float v0 = (acc[i][j][ph * 2 + 0] + qr[d0 + 50]) * 0.125f;
                float v1 = (acc[i][j][ph * 2 + 1] + qr[d1 + 50]) * 0.125f;
                *(float2*)&outr[kki] = make_float2(v0, v1);
            }
        }
}

// ---------------- softmax + relative-position buckets ------------------------
__global__ void __launch_bounds__(256)
softmax_kernel(float* __restrict__ attn) {
    __shared__ float sp[1024];
    __shared__ float red[8];
    int row = blockIdx.x;               // bh*1024 + q
    int qq = row & 1023;
    float* p = attn + (size_t)row * ASTRIDE;
    int tid = threadIdx.x;
    float4 v = *(const float4*)&p[tid * 4];
    float m = fmaxf(fmaxf(v.x, v.y), fmaxf(v.z, v.w));
    m = blk_reduce(m, red, true);
    float e0 = expf(v.x - m), e1 = expf(v.y - m);
    float e2 = expf(v.z - m), e3 = expf(v.w - m);
    float s = blk_reduce(e0 + e1 + e2 + e3, red, false);
    float inv = 1.0f / s;
    e0 *= inv; e1 *= inv; e2 *= inv; e3 *= inv;
    *(float4*)&p[tid * 4] = make_float4(e0, e1, e2, e3);
    sp[tid * 4 + 0] = e0; sp[tid * 4 + 1] = e1;
    sp[tid * 4 + 2] = e2; sp[tid * 4 + 3] = e3;
    __syncthreads();
    int lo = qq - 50, hi = qq + 50;
    float s0 = 0.f, s100 = 0.f;
    for (int kk = tid; kk < 1024; kk += 256) {
        float pv = sp[kk];
        if (kk <= lo) s0 += pv;
        if (kk >= hi) s100 += pv;
    }
    s0 = blk_reduce(s0, red, false);
    s100 = blk_reduce(s100, red, false);
    if (tid == 0) { p[1024] = s0; p[1024 + 100] = s100; }
    if (tid >= 1 && tid < 100) {
        int kk = qq + tid - 50;
        p[1024 + tid] = (kk >= 0 && kk < 1024) ? sp[kk] : 0.0f;
    }
    if (tid >= 100 && tid < 127) p[1025 + tid] = 0.0f;  // zero pad 1125..1151
}

// ---------------- AV (K-extended with rel_v), tf32 mma -----------------------
// Block 128q x 64d, K loop over 1152 (zero-padded). 8 warps as 4(m) x 2(n),
// warp tile 32x32.
__global__ void __launch_bounds__(256)
av_kernel(const float* __restrict__ attn, const float* __restrict__ v,
          const float* __restrict__ relv, float* __restrict__ o) {
    __shared__ uint32_t sP[32][132];
    __shared__ uint32_t sV[32][68];
    int bh = blockIdx.y;
    int b = bh >> 4, hd = bh & 15;
    int q0 = blockIdx.x * 128;
    int tid = threadIdx.x;
    int warp = tid >> 5, lane = tid & 31;
    int wm = (warp & 3) * 32, wn = (warp >> 2) * 32;
    int r = lane >> 2, cq = lane & 3;
    const float* Arow = attn + ((size_t)bh * 1024 + q0) * ASTRIDE;
    int prow = tid >> 1, pcg = (tid & 1) * 16;
    int vr = tid >> 3, vcg = (tid & 7) * 8;
    float acc[2][4][4] = {};
    for (int kt = 0; kt < 36; kt++) {
        int k0 = kt * 32;
        #pragma unroll
        for (int it = 0; it < 4; it++) {
            int c = pcg + it * 4;
            float4 a = *(const float4*)&Arow[(size_t)prow * ASTRIDE + k0 + c];
            sP[c + 0][prow] = f2tf(a.x); sP[c + 1][prow] = f2tf(a.y);
            sP[c + 2][prow] = f2tf(a.z); sP[c + 3][prow] = f2tf(a.w);
        }
        {
            int kk = k0 + vr;
            #pragma unroll
            for (int it = 0; it < 2; it++) {
                int c = vcg + it * 4;
                float4 bvv;
                if (kk < 1024)
                    bvv = *(const float4*)&v[((size_t)(b * S_LEN) + kk) * DMODEL + hd * HDIM + c];
                else if (kk < KEXT)
                    bvv = *(const float4*)&relv[(size_t)(kk - 1024) * HDIM + c];
                else
                    bvv = make_float4(0.f, 0.f, 0.f, 0.f);
                sV[vr][c + 0] = f2tf(bvv.x); sV[vr][c + 1] = f2tf(bvv.y);
                sV[vr][c + 2] = f2tf(bvv.z); sV[vr][c + 3] = f2tf(bvv.w);
            }
        }
        __syncthreads();
        #pragma unroll
        for (int kk = 0; kk < 32; kk += 8) {
            uint32_t af[2][4], bf[4][2];
            #pragma unroll
            for (int i = 0; i < 2; i++) {
                int mi = wm + i * 16 + r;
                af[i][0] = sP[kk + cq][mi];     af[i][1] = sP[kk + cq][mi + 8];
                af[i][2] = sP[kk + cq + 4][mi]; af[i][3] = sP[kk + cq + 4][mi + 8];
            }
            #pragma unroll
            for (int j = 0; j < 4; j++) {
                int nj = wn + j * 8 + r;
                bf[j][0] = sV[kk + cq][nj];
                bf[j][1] = sV[kk + cq + 4][nj];
            }
            #pragma unroll
            for (int i = 0; i < 2; i++)
                #pragma unroll
                for (int j = 0; j < 4; j++)
                    mma8(acc[i][j], af[i], bf[j]);
        }
        __syncthreads();
    }
    #pragma unroll
    for (int i = 0; i < 2; i++)
        #pragma unroll
        for (int ph = 0; ph < 2; ph++) {
            int qq = q0 + wm + i * 16 + r + ph * 8;
            float* op = o + ((size_t)(b * S_LEN) + qq) * DMODEL + hd * HDIM;
            #pragma unroll
            for (int j = 0; j < 4; j++) {
                int col = wn + j * 8 + 2 * cq;
                *(float2*)&op[col] =
                    make_float2(acc[i][j][ph * 2 + 0], acc[i][j][ph * 2 + 1]);
            }
        }
}

// ---------------- host launch -------------------------------------------------
extern "C" void kernel_launch(void* const* d_in, const int* in_sizes, int n_in,
                              void* d_out, int out_size) {
    const float* x     = (const float*)d_in[0];
    const float* Wq    = (const float*)d_in[1];
    const float* bq    = (const float*)d_in[2];
    const float* Wk    = (const float*)d_in[3];
    const float* bk    = (const float*)d_in[4];
    const float* Wv    = (const float*)d_in[5];
    const float* bv    = (const float*)d_in[6];
    const float* Wo    = (const float*)d_in[7];
    const float* bo    = (const float*)d_in[8];
    const float* rel_k = (const float*)d_in[9];
    const float* rel_v = (const float*)d_in[10];
    const float* ga    = (const float*)d_in[11];
    const float* gf    = (const float*)d_in[12];
    const float* W_in  = (const float*)d_in[13];
    const float* b_in  = (const float*)d_in[14];
    const float* W_out = (const float*)d_in[15];
    const float* b_out = (const float*)d_in[16];
    float* out = (float*)d_out;

    float *hn, *qb, *kb, *vb, *qr, *at, *ob, *h2, *ffin, *gel;
    cudaGetSymbolAddress((void**)&hn,   g_hn);
    cudaGetSymbolAddress((void**)&qb,   g_q);
    cudaGetSymbolAddress((void**)&kb,   g_k);
    cudaGetSymbolAddress((void**)&vb,   g_v);
    cudaGetSymbolAddress((void**)&qr,   g_qrel);
    cudaGetSymbolAddress((void**)&at,   g_attn);
    cudaGetSymbolAddress((void**)&ob,   g_o);
    cudaGetSymbolAddress((void**)&h2,   g_h2);
    cudaGetSymbolAddress((void**)&ffin, g_ffin);
    cudaGetSymbolAddress((void**)&gel,  g_gelu);

    // 1. h = rmsnorm(x, g_attn), transpose [S,B,D] -> [B,S,D]
    rmsnorm_kernel<<<M4, 256>>>(x, ga, hn, 1);
    // 2. q, k, v  (tf32 tensor cores)
    dim3 g1(DMODEL / 128, M4 / 128);
    tgemm_kernel<0><<<g1, 256>>>(hn, Wq, bq, nullptr, qb, M4, DMODEL, DMODEL);
    tgemm_kernel<0><<<g1, 256>>>(hn, Wk, bk, nullptr, kb, M4, DMODEL, DMODEL);
    tgemm_kernel<0><<<g1, 256>>>(hn, Wv, bv, nullptr, vb, M4, DMODEL, DMODEL);
    // 3. qrel
    qrel_kernel<<<dim3(16, 64), 256>>>(qb, rel_k, qr);
    // 4. scores (tf32 mma)
    score_kernel<<<dim3(16, 16, 64), 256>>>(qb, kb, qr, at);
    // 5. softmax + buckets
    softmax_kernel<<<65536, 256>>>(at);
    // 6. AV (with rel_v K-extension, tf32 mma)
    av_kernel<<<dim3(8, 64), 256>>>(at, vb, rel_v, ob);
    // 7. h2 = hn + o @ Wo^T + bo
    tgemm_kernel<2><<<g1, 256>>>(ob, Wo, bo, hn, h2, M4, DMODEL, DMODEL);
    // 8. ffin = rmsnorm(h2, g_ff)
    rmsnorm_kernel<<<M4, 256>>>(h2, gf, ffin, 0);
    // 9. gelu(ffin @ W_in^T + b_in)
    tgemm_kernel<1><<<dim3(DFF / 128, M4 / 128), 256>>>(ffin, W_in, b_in, nullptr,
                                                        gel, M4, DFF, DMODEL);
    // 10. out = h2 + gel @ W_out^T + b_out  (written back in [S,B,D] order)
    tgemm_kernel<3><<<g1, 256>>>(gel, W_out, b_out, h2, out, M4, DMODEL, DFF);
}

// round 5
// speedup vs baseline: 2.0649x; 1.2722x over previous
#include <cuda_runtime.h>
#include <cuda_bf16.h>
#include <math.h>
#include <stdint.h>

// Problem constants
#define S_LEN 1024
#define BATCH 4
#define DMODEL 1024
#define NHEAD 16
#define HDIM 64
#define M4 4096          // BATCH * S_LEN
#define DFF 4096
#define NREL 101         // 2*MAXREL+1
#define ASTRIDE 1152     // 1024 p + 101 bucket + 27 zero pad
#define KEXT 1125        // 1024 + 101

// ---------------- scratch (device globals; no allocations allowed) ----------
__device__ float g_hn  [M4 * DMODEL];          // rmsnorm(x) in [B,S,D] order
__device__ float g_q   [M4 * DMODEL];
__device__ float g_k   [M4 * DMODEL];
__device__ float g_v   [M4 * DMODEL];
__device__ float g_qrel[64 * 1024 * NREL];     // [bh, q, r]
__device__ float g_attn[75497472];             // [bh, q, ASTRIDE] = 64*1024*1152
__device__ float g_o   [M4 * DMODEL];          // attention head outputs [B,S,D]
__device__ float g_h2  [M4 * DMODEL];          // h + attn_out
__device__ float g_ffin[M4 * DMODEL];          // rmsnorm(h2)
__device__ float g_gelu[(size_t)M4 * DFF];     // gelu(ff @ W_in^T + b_in)

// ---------------- helpers ----------------------------------------------------
__device__ __forceinline__ float gelu_f(float x) {
    return 0.5f * x * (1.0f + erff(x * 0.70710678118654752f));
}

__device__ __forceinline__ uint32_t f2tf(float f) {
    uint32_t u;
    asm("cvt.rna.tf32.f32 %0, %1;" : "=r"(u) : "f"(f));
    return u;
}

// D = A(16x8, row) * B(8x8, col) + D   (tf32 inputs, f32 accum)
__device__ __forceinline__ void mma8(float* c, const uint32_t* a, const uint32_t* b) {
    asm volatile(
        "mma.sync.aligned.m16n8k8.row.col.f32.tf32.tf32.f32 "
        "{%0,%1,%2,%3}, {%4,%5,%6,%7}, {%8,%9}, {%0,%1,%2,%3};"
        : "+f"(c[0]), "+f"(c[1]), "+f"(c[2]), "+f"(c[3])
        : "r"(a[0]), "r"(a[1]), "r"(a[2]), "r"(a[3]), "r"(b[0]), "r"(b[1]));
}

__device__ __forceinline__ void cpa16(uint32_t smem, const void* gmem) {
    asm volatile("cp.async.cg.shared.global [%0], [%1], 16;\n"
                 :: "r"(smem), "l"(gmem));
}
__device__ __forceinline__ void cpa_commit() {
    asm volatile("cp.async.commit_group;\n");
}
template <int N>
__device__ __forceinline__ void cpa_wait() {
    asm volatile("cp.async.wait_group %0;\n" :: "n"(N));
}

// 256-thread block reduce (8 warps). domax: true -> max, false -> sum.
__device__ __forceinline__ float blk_reduce(float v, float* red, bool domax) {
    #pragma unroll
    for (int o = 16; o > 0; o >>= 1) {
        float u = __shfl_xor_sync(0xffffffffu, v, o);
        v = domax ? fmaxf(v, u) : (v + u);
    }
    __syncthreads();
    if ((threadIdx.x & 31) == 0) red[threadIdx.x >> 5] = v;
    __syncthreads();
    float t = red[0];
    #pragma unroll
    for (int i = 1; i < 8; i++) t = domax ? fmaxf(t, red[i]) : (t + red[i]);
    return t;
}

// ---------------- RMSNorm -----------------------------------------------------
__global__ void __launch_bounds__(256)
rmsnorm_kernel(const float* __restrict__ in, const float* __restrict__ g,
               float* __restrict__ out, int transpose_in) {
    __shared__ float red[8];
    int row = blockIdx.x;
    int tid = threadIdx.x;
    const float* xr = in + (size_t)row * DMODEL;
    float4 v = *(const float4*)&xr[tid * 4];
    float ss = v.x * v.x + v.y * v.y + v.z * v.z + v.w * v.w;
    ss = blk_reduce(ss, red, false);
    float rms = sqrtf(ss) * 0.03125f;                // /sqrt(1024)
    float inv = 1.0f / (rms + 1e-8f);
    float4 gv = *(const float4*)&g[tid * 4];
    float4 o = make_float4(v.x * inv * gv.x, v.y * inv * gv.y,
                           v.z * inv * gv.z, v.w * inv * gv.w);
    size_t orow = row;
    if (transpose_in) {
        int s = row >> 2, b = row & 3;               // row = s*B+b
        orow = ((size_t)b << 10) + s;                // out row = b*S+s
    }
    *(float4*)&out[orow * DMODEL + tid * 4] = o;
}

// ---------------- tf32 tensor-core GEMM, cp.async double-buffered -------------
// C[M,N] = A[M,K] @ W[N,K]^T
// EPI: 0 = +bias ; 1 = +bias,gelu ; 2 = +bias,+res[m*1024+n] ;
//      3 = +bias,+res[m*1024+n], transposed write out[(s*B+b)*D + n]
// M%128==0, N%128==0, K%16==0. 256 threads, warps 2(m) x 4(n), warp 64x32.
// smem [m][k] raw fp32 bits; mma consumes raw bits as tf32 (truncation).
template <int EPI>
__global__ void __launch_bounds__(256, 2)
tgemm_kernel(const float* __restrict__ A, const float* __restrict__ W,
             const float* __restrict__ bias, const float* __restrict__ res,
             float* __restrict__ C, int M, int N, int K) {
    __shared__ uint32_t sA[2][128][20];   // KT=16 + pad4 (conflict-free frag LDS)
    __shared__ uint32_t sB[2][128][20];
    int tid = threadIdx.x;
    int m0 = blockIdx.y * 128, n0 = blockIdx.x * 128;
    int warp = tid >> 5, lane = tid & 31;
    int wm = (warp & 1) * 64, wn = (warp >> 1) * 32;
    int r = lane >> 2, cq = lane & 3;

    // cp.async mapping: 512 16B-chunks per tile; thread handles chunks tid, tid+256
    int ar0 = tid >> 2,          ak0 = (tid & 3) * 4;
    int ar1 = (tid + 256) >> 2,  ak1 = (tid & 3) * 4;   // (tid+256)&3 == tid&3
    const float* Ag0 = A + (size_t)(m0 + ar0) * K + ak0;
    const float* Ag1 = A + (size_t)(m0 + ar1) * K + ak1;
    const float* Wg0 = W + (size_t)(n0 + ar0) * K + ak0;
    const float* Wg1 = W + (size_t)(n0 + ar1) * K + ak1;
    uint32_t dA0[2], dA1[2], dB0[2], dB1[2];
    #pragma unroll
    for (int s = 0; s < 2; s++) {
        dA0[s] = (uint32_t)__cvta_generic_to_shared(&sA[s][ar0][ak0]);
        dA1[s] = (uint32_t)__cvta_generic_to_shared(&sA[s][ar1][ak1]);
        dB0[s] = (uint32_t)__cvta_generic_to_shared(&sB[s][ar0][ak0]);
        dB1[s] = (uint32_t)__cvta_generic_to_shared(&sB[s][ar1][ak1]);
    }

    float acc[4][4][4] = {};
    int T = K >> 4;
    // prologue: stage 0
    cpa16(dA0[0], Ag0); cpa16(dA1[0], Ag1);
    cpa16(dB0[0], Wg0); cpa16(dB1[0], Wg1);
    cpa_commit();

    for (int t = 0; t < T; t++) {
        if (t + 1 < T) {
            int st = (t + 1) & 1;
            int k0 = (t + 1) << 4;
            cpa16(dA0[st], Ag0 + k0); cpa16(dA1[st], Ag1 + k0);
            cpa16(dB0[st], Wg0 + k0); cpa16(dB1[st], Wg1 + k0);
            cpa_commit();
            cpa_wait<1>();
        } else {
            cpa_wait<0>();
        }
        __syncthreads();
        const uint32_t (*pA)[20] = sA[t & 1];
        const uint32_t (*pB)[20] = sB[t & 1];
        #pragma unroll
        for (int kk = 0; kk < 16; kk += 8) {
            uint32_t af[4][4], bf[4][2];
            #pragma unroll
            for (int i = 0; i < 4; i++) {
                int mi = wm + i * 16 + r;
                af[i][0] = pA[mi][kk + cq];     af[i][1] = pA[mi + 8][kk + cq];
                af[i][2] = pA[mi][kk + cq + 4]; af[i][3] = pA[mi + 8][kk + cq + 4];
            }
            #pragma unroll
            for (int j = 0; j < 4; j++) {
                int nj = wn + j * 8 + r;
                bf[j][0] = pB[nj][kk + cq];
                bf[j][1] = pB[nj][kk + cq + 4];
            }
            #pragma unroll
            for (int i = 0; i < 4; i++)
                #pragma unroll
                for (int j = 0; j < 4; j++)
                    mma8(acc[i][j], af[i], bf[j]);
        }
        __syncthreads();
    }
    // epilogue
    float2 bb[4];
    #pragma unroll
    for (int j = 0; j < 4; j++)
        bb[j] = *(const float2*)&bias[n0 + wn + j * 8 + 2 * cq];
    #pragma unroll
    for (int i = 0; i < 4; i++)
        #pragma unroll
        for (int ph = 0; ph < 2; ph++) {
            int m = m0 + wm + i * 16 + r + ph * 8;
            #pragma unroll
            for (int j = 0; j < 4; j++) {
                int col = n0 + wn + j * 8 + 2 * cq;
                float v0 = acc[i][j][ph * 2 + 0] + bb[j].x;
                float v1 = acc[i][j][ph * 2 + 1] + bb[j].y;
                if (EPI == 1) { v0 = gelu_f(v0); v1 = gelu_f(v1); }
                if (EPI == 2 || EPI == 3) {
                    float2 rr = *(const float2*)&res[(size_t)m * 1024 + col];
                    v0 += rr.x; v1 += rr.y;
                }
                size_t ob;
                if (EPI == 3) {
                    int b = m >> 10, s = m & 1023;
                    ob = ((size_t)(s * BATCH + b)) * DMODEL + col;
                } else {
                    ob = (size_t)m * N + col;
                }
                *(float2*)&C[ob] = make_float2(v0, v1);
            }
        }
}

// ---------------- qrel: qrel[bh,q,r] = q_head[q,:] . rel_k[r,:] ---------------
__global__ void __launch_bounds__(256)
qrel_kernel(const float* __restrict__ q, const float* __restrict__ relk,
            float* __restrict__ qrel) {
    __shared__ float sR[NREL][65];
    __shared__ float sQ[64][65];
    int bh = blockIdx.y;
    int b = bh >> 4, h = bh & 15;
    int q0 = blockIdx.x * 64;
    int tid = threadIdx.x;
    const float* Q = q + ((size_t)(b * S_LEN) + q0) * DMODEL + h * HDIM;
    for (int i = tid; i < NREL * 64; i += 256) {
        int r = i >> 6, d = i & 63;
        sR[r][d] = relk[i];
    }
    for (int i = tid; i < 64 * 64; i += 256) {
        int r = i >> 6, d = i & 63;
        sQ[r][d] = Q[(size_t)r * DMODEL + d];
    }
    __syncthreads();
    for (int i = tid; i < 64 * NREL; i += 256) {
        int qq = i / NREL, r = i % NREL;
        float s = 0.f;
        #pragma unroll
        for (int d = 0; d < 64; d++) s += sQ[qq][d] * sR[r][d];
        qrel[((size_t)bh * 1024 + q0 + qq) * NREL + r] = s;
    }
}

// ---------------- scores: attn[bh,q,k] = (q.k + qrel[clip(k-q)]) / 8 ----------
// tf32 mma: 64x64 tile, K=64. 8 warps as 2(m) x 4(n), warp 32x16.
__global__ void __launch_bounds__(256)
score_kernel(const float* __restrict__ q, const float* __restrict__ k,
             const float* __restrict__ qrel, float* __restrict__ attn) {
    __shared__ uint32_t sQ[64][68];
    __shared__ uint32_t sK[64][68];
    int bh = blockIdx.z;
    int b = bh >> 4, hd = bh & 15;
    int q0 = blockIdx.y * 64, k0 = blockIdx.x * 64;
    int tid = threadIdx.x;
    const float* Q  = q + ((size_t)(b * S_LEN) + q0) * DMODEL + hd * HDIM;
    const float* Kp = k + ((size_t)(b * S_LEN) + k0) * DMODEL + hd * HDIM;
    int lrow = tid >> 2, lcg = (tid & 3) * 16;
    #pragma unroll
    for (int it = 0; it < 4; it++) {
        int c = lcg + it * 4;
        float4 v = *(const float4*)&Q[(size_t)lrow * DMODEL + c];
        sQ[c + 0][lrow] = f2tf(v.x); sQ[c + 1][lrow] = f2tf(v.y);
        sQ[c + 2][lrow] = f2tf(v.z); sQ[c + 3][lrow] = f2tf(v.w);
        float4 w = *(const float4*)&Kp[(size_t)lrow * DMODEL + c];
        sK[c + 0][lrow] = f2tf(w.x); sK[c + 1][lrow] = f2tf(w.y);
        sK[c + 2][lrow] = f2tf(w.z); sK[c + 3][lrow] = f2tf(w.w);
    }
    __syncthreads();
    int warp = tid >> 5, lane = tid & 31;
    int wm = (warp & 1) * 32, wn = (warp >> 1) * 16;
    int r = lane >> 2, cq = lane & 3;
    float acc[2][2][4] = {};
    #pragma unroll
    for (int kk = 0; kk < 64; kk += 8) {
        uint32_t af[2][4], bf[2][2];
        #pragma unroll
        for (int i = 0; i < 2; i++) {
            int mi = wm + i * 16 + r;
            af[i][0] = sQ[kk + cq][mi];     af[i][1] = sQ[kk + cq][mi + 8];
            af[i][2] = sQ[kk + cq + 4][mi]; af[i][3] = sQ[kk + cq + 4][mi + 8];
        }
        #pragma unroll
        for (int j = 0; j < 2; j++) {
            int nj = wn + j * 8 + r;
            bf[j][0] = sK[kk + cq][nj];
            bf[j][1] = sK[kk + cq + 4][nj];
        }
        #pragma unroll
        for (int i = 0; i < 2; i++)
            #pragma unroll
            for (int j = 0; j < 2; j++)
                mma8(acc[i][j], af[i], bf[j]);
    }
    size_t rowbase = (size_t)bh * 1024;
    #pragma unroll
    for (int i = 0; i < 2; i++)
        #pragma unroll
        for (int ph = 0; ph < 2; ph++) {
            int qq = q0 + wm + i * 16 + r + ph * 8;
            const float* qr = qrel + (rowbase + qq) * NREL;
            float* outr = attn + (rowbase + qq) * ASTRIDE;
            #pragma unroll
            for (int j = 0; j < 2; j++) {
                int kki = k0 + wn + j * 8 + 2 * cq;
                int d0 = min(max(kki - qq, -50), 50);
                int d1 = min(max(kki + 1 - qq, -50), 50);
                float v0 = (acc[i][j][ph * 2 + 0] + qr[d0 + 50]) * 0.125f;
                float v1 = (acc[i][j][ph * 2 + 1] + qr[d1 + 50]) * 0.125f;
                *(float2*)&outr[kki] = make_float2(v0, v1);
            }
        }
}

// ---------------- softmax + relative-position buckets ------------------------
__global__ void __launch_bounds__(256)
softmax_kernel(float* __restrict__ attn) {
    __shared__ float sp[1024];
    __shared__ float red[8];
    int row = blockIdx.x;               // bh*1024 + q
    int qq = row & 1023;
    float* p = attn + (size_t)row * ASTRIDE;
    int tid = threadIdx.x;
    float4 v = *(const float4*)&p[tid * 4];
    float m = fmaxf(fmaxf(v.x, v.y), fmaxf(v.z, v.w));
    m = blk_reduce(m, red, true);
    float e0 = expf(v.x - m), e1 = expf(v.y - m);
    float e2 = expf(v.z - m), e3 = expf(v.w - m);
    float s = blk_reduce(e0 + e1 + e2 + e3, red, false);
    float inv = 1.0f / s;
    e0 *= inv; e1 *= inv; e2 *= inv; e3 *= inv;
    *(float4*)&p[tid * 4] = make_float4(e0, e1, e2, e3);
    sp[tid * 4 + 0] = e0; sp[tid * 4 + 1] = e1;
    sp[tid * 4 + 2] = e2; sp[tid * 4 + 3] = e3;
    __syncthreads();
    int lo = qq - 50, hi = qq + 50;
    float s0 = 0.f, s100 = 0.f;
    for (int kk = tid; kk < 1024; kk += 256) {
        float pv = sp[kk];
        if (kk <= lo) s0 += pv;
        if (kk >= hi) s100 += pv;
    }
    s0 = blk_reduce(s0, red, false);
    s100 = blk_reduce(s100, red, false);
    if (tid == 0) { p[1024] = s0; p[1024 + 100] = s100; }
    if (tid >= 1 && tid < 100) {
        int kk = qq + tid - 50;
        p[1024 + tid] = (kk >= 0 && kk < 1024) ? sp[kk] : 0.0f;
    }
    if (tid >= 100 && tid < 127) p[1025 + tid] = 0.0f;  // zero pad 1125..1151
}

// ---------------- AV (K-extended with rel_v), tf32 mma -----------------------
// Block 128q x 64d, K loop over 1152 (zero-padded). 8 warps as 4(m) x 2(n),
// warp tile 32x32.
__global__ void __launch_bounds__(256)
av_kernel(const float* __restrict__ attn, const float* __restrict__ v,
          const float* __restrict__ relv, float* __restrict__ o) {
    __shared__ uint32_t sP[32][132];
    __shared__ uint32_t sV[32][68];
    int bh = blockIdx.y;
    int b = bh >> 4, hd = bh & 15;
    int q0 = blockIdx.x * 128;
    int tid = threadIdx.x;
    int warp = tid >> 5, lane = tid & 31;
    int wm = (warp & 3) * 32, wn = (warp >> 2) * 32;
    int r = lane >> 2, cq = lane & 3;
    const float* Arow = attn + ((size_t)bh * 1024 + q0) * ASTRIDE;
    int prow = tid >> 1, pcg = (tid & 1) * 16;
    int vr = tid >> 3, vcg = (tid & 7) * 8;
    float acc[2][4][4] = {};
    for (int kt = 0; kt < 36; kt++) {
        int k0 = kt * 32;
        #pragma unroll
        for (int it = 0; it < 4; it++) {
            int c = pcg + it * 4;
            float4 a = *(const float4*)&Arow[(size_t)prow * ASTRIDE + k0 + c];
            sP[c + 0][prow] = f2tf(a.x); sP[c + 1][prow] = f2tf(a.y);
            sP[c + 2][prow] = f2tf(a.z); sP[c + 3][prow] = f2tf(a.w);
        }
        {
            int kk = k0 + vr;
            #pragma unroll
            for (int it = 0; it < 2; it++) {
                int c = vcg + it * 4;
                float4 bvv;
                if (kk < 1024)
                    bvv = *(const float4*)&v[((size_t)(b * S_LEN) + kk) * DMODEL + hd * HDIM + c];
                else if (kk < KEXT)
                    bvv = *(const float4*)&relv[(size_t)(kk - 1024) * HDIM + c];
                else
                    bvv = make_float4(0.f, 0.f, 0.f, 0.f);
                sV[vr][c + 0] = f2tf(bvv.x); sV[vr][c + 1] = f2tf(bvv.y);
                sV[vr][c + 2] = f2tf(bvv.z); sV[vr][c + 3] = f2tf(bvv.w);
            }
        }
        __syncthreads();
        #pragma unroll
        for (int kk = 0; kk < 32; kk += 8) {
            uint32_t af[2][4], bf[4][2];
            #pragma unroll
            for (int i = 0; i < 2; i++) {
                int mi = wm + i * 16 + r;
                af[i][0] = sP[kk + cq][mi];     af[i][1] = sP[kk + cq][mi + 8];
                af[i][2] = sP[kk + cq + 4][mi]; af[i][3] = sP[kk + cq + 4][mi + 8];
            }
            #pragma unroll
            for (int j = 0; j < 4; j++) {
                int nj = wn + j * 8 + r;
                bf[j][0] = sV[kk + cq][nj];
                bf[j][1] = sV[kk + cq + 4][nj];
            }
            #pragma unroll
            for (int i = 0; i < 2; i++)
                #pragma unroll
                for (int j = 0; j < 4; j++)
                    mma8(acc[i][j], af[i], bf[j]);
        }
        __syncthreads();
    }
    #pragma unroll
    for (int i = 0; i < 2; i++)
        #pragma unroll
        for (int ph = 0; ph < 2; ph++) {
            int qq = q0 + wm + i * 16 + r + ph * 8;
            float* op = o + ((size_t)(b * S_LEN) + qq) * DMODEL + hd * HDIM;
            #pragma unroll
            for (int j = 0; j < 4; j++) {
                int col = wn + j * 8 + 2 * cq;
                *(float2*)&op[col] =
                    make_float2(acc[i][j][ph * 2 + 0], acc[i][j][ph * 2 + 1]);
            }
        }
}

// ---------------- host launch -------------------------------------------------
extern "C" void kernel_launch(void* const* d_in, const int* in_sizes, int n_in,
                              void* d_out, int out_size) {
    const float* x     = (const float*)d_in[0];
    const float* Wq    = (const float*)d_in[1];
    const float* bq    = (const float*)d_in[2];
    const float* Wk    = (const float*)d_in[3];
    const float* bk    = (const float*)d_in[4];
    const float* Wv    = (const float*)d_in[5];
    const float* bv    = (const float*)d_in[6];
    const float* Wo    = (const float*)d_in[7];
    const float* bo    = (const float*)d_in[8];
    const float* rel_k = (const float*)d_in[9];
    const float* rel_v = (const float*)d_in[10];
    const float* ga    = (const float*)d_in[11];
    const float* gf    = (const float*)d_in[12];
    const float* W_in  = (const float*)d_in[13];
    const float* b_in  = (const float*)d_in[14];
    const float* W_out = (const float*)d_in[15];
    const float* b_out = (const float*)d_in[16];
    float* out = (float*)d_out;

    float *hn, *qb, *kb, *vb, *qr, *at, *ob, *h2, *ffin, *gel;
    cudaGetSymbolAddress((void**)&hn,   g_hn);
    cudaGetSymbolAddress((void**)&qb,   g_q);
    cudaGetSymbolAddress((void**)&kb,   g_k);
    cudaGetSymbolAddress((void**)&vb,   g_v);
    cudaGetSymbolAddress((void**)&qr,   g_qrel);
    cudaGetSymbolAddress((void**)&at,   g_attn);
    cudaGetSymbolAddress((void**)&ob,   g_o);
    cudaGetSymbolAddress((void**)&h2,   g_h2);
    cudaGetSymbolAddress((void**)&ffin, g_ffin);
    cudaGetSymbolAddress((void**)&gel,  g_gelu);

    // 1. h = rmsnorm(x, g_attn), transpose [S,B,D] -> [B,S,D]
    rmsnorm_kernel<<<M4, 256>>>(x, ga, hn, 1);
    // 2. q, k, v  (tf32 tensor cores, cp.async pipelined)
    dim3 g1(DMODEL / 128, M4 / 128);
    tgemm_kernel<0><<<g1, 256>>>(hn, Wq, bq, nullptr, qb, M4, DMODEL, DMODEL);
    tgemm_kernel<0><<<g1, 256>>>(hn, Wk, bk, nullptr, kb, M4, DMODEL, DMODEL);
    tgemm_kernel<0><<<g1, 256>>>(hn, Wv, bv, nullptr, vb, M4, DMODEL, DMODEL);
    // 3. qrel
    qrel_kernel<<<dim3(16, 64), 256>>>(qb, rel_k, qr);
    // 4. scores (tf32 mma)
    score_kernel<<<dim3(16, 16, 64), 256>>>(qb, kb, qr, at);
    // 5. softmax + buckets
    softmax_kernel<<<65536, 256>>>(at);
    // 6. AV (with rel_v K-extension, tf32 mma)
    av_kernel<<<dim3(8, 64), 256>>>(at, vb, rel_v, ob);
    // 7. h2 = hn + o @ Wo^T + bo
    tgemm_kernel<2><<<g1, 256>>>(ob, Wo, bo, hn, h2, M4, DMODEL, DMODEL);
    // 8. ffin = rmsnorm(h2, g_ff)
    rmsnorm_kernel<<<M4, 256>>>(h2, gf, ffin, 0);
    // 9. gelu(ffin @ W_in^T + b_in)
    tgemm_kernel<1><<<dim3(DFF / 128, M4 / 128), 256>>>(ffin, W_in, b_in, nullptr,
                                                        gel, M4, DFF, DMODEL);
    // 10. out = h2 + gel @ W_out^T + b_out  (written back in [S,B,D] order)
    tgemm_kernel<3><<<g1, 256>>>(gel, W_out, b_out, h2, out, M4, DMODEL, DFF);
}

// round 6
// speedup vs baseline: 2.7575x; 1.3355x over previous
#include <cuda_runtime.h>
#include <cuda_bf16.h>
#include <math.h>
#include <stdint.h>

// Problem constants
#define S_LEN 1024
#define BATCH 4
#define DMODEL 1024
#define NHEAD 16
#define HDIM 64
#define M4 4096          // BATCH * S_LEN
#define DFF 4096
#define NREL 101         // 2*MAXREL+1

// ---------------- scratch (device globals; no allocations allowed) ----------
__device__ float g_hn  [M4 * DMODEL];          // rmsnorm(x) in [B,S,D] order
__device__ float g_q   [M4 * DMODEL];
__device__ float g_k   [M4 * DMODEL];
__device__ float g_v   [M4 * DMODEL];
__device__ float g_qrel[64 * 1024 * NREL];     // [bh, q, r]
__device__ float g_o   [M4 * DMODEL];          // attention head outputs [B,S,D]
__device__ float g_h2  [M4 * DMODEL];          // h + attn_out
__device__ float g_ffin[M4 * DMODEL];          // rmsnorm(h2)
__device__ float g_gelu[(size_t)M4 * DFF];     // gelu(ff @ W_in^T + b_in)

// ---------------- helpers ----------------------------------------------------
__device__ __forceinline__ float gelu_f(float x) {
    return 0.5f * x * (1.0f + erff(x * 0.70710678118654752f));
}

__device__ __forceinline__ uint32_t f2tf(float f) {
    uint32_t u;
    asm("cvt.rna.tf32.f32 %0, %1;" : "=r"(u) : "f"(f));
    return u;
}

// D = A(16x8, row) * B(8x8, col) + D   (tf32 inputs, f32 accum)
__device__ __forceinline__ void mma8(float* c, const uint32_t* a, const uint32_t* b) {
    asm volatile(
        "mma.sync.aligned.m16n8k8.row.col.f32.tf32.tf32.f32 "
        "{%0,%1,%2,%3}, {%4,%5,%6,%7}, {%8,%9}, {%0,%1,%2,%3};"
        : "+f"(c[0]), "+f"(c[1]), "+f"(c[2]), "+f"(c[3])
        : "r"(a[0]), "r"(a[1]), "r"(a[2]), "r"(a[3]), "r"(b[0]), "r"(b[1]));
}

__device__ __forceinline__ void cpa16(uint32_t smem, const void* gmem) {
    asm volatile("cp.async.cg.shared.global [%0], [%1], 16;\n"
                 :: "r"(smem), "l"(gmem));
}
__device__ __forceinline__ void cpa_commit() {
    asm volatile("cp.async.commit_group;\n");
}
template <int N>
__device__ __forceinline__ void cpa_wait() {
    asm volatile("cp.async.wait_group %0;\n" :: "n"(N));
}

// 256-thread block reduce (8 warps). domax: true -> max, false -> sum.
__device__ __forceinline__ float blk_reduce(float v, float* red, bool domax) {
    #pragma unroll
    for (int o = 16; o > 0; o >>= 1) {
        float u = __shfl_xor_sync(0xffffffffu, v, o);
        v = domax ? fmaxf(v, u) : (v + u);
    }
    __syncthreads();
    if ((threadIdx.x & 31) == 0) red[threadIdx.x >> 5] = v;
    __syncthreads();
    float t = red[0];
    #pragma unroll
    for (int i = 1; i < 8; i++) t = domax ? fmaxf(t, red[i]) : (t + red[i]);
    return t;
}

// ---------------- RMSNorm -----------------------------------------------------
__global__ void __launch_bounds__(256)
rmsnorm_kernel(const float* __restrict__ in, const float* __restrict__ g,
               float* __restrict__ out, int transpose_in) {
    __shared__ float red[8];
    int row = blockIdx.x;
    int tid = threadIdx.x;
    const float* xr = in + (size_t)row * DMODEL;
    float4 v = *(const float4*)&xr[tid * 4];
    float ss = v.x * v.x + v.y * v.y + v.z * v.z + v.w * v.w;
    ss = blk_reduce(ss, red, false);
    float rms = sqrtf(ss) * 0.03125f;                // /sqrt(1024)
    float inv = 1.0f / (rms + 1e-8f);
    float4 gv = *(const float4*)&g[tid * 4];
    float4 o = make_float4(v.x * inv * gv.x, v.y * inv * gv.y,
                           v.z * inv * gv.z, v.w * inv * gv.w);
    size_t orow = row;
    if (transpose_in) {
        int s = row >> 2, b = row & 3;               // row = s*B+b
        orow = ((size_t)b << 10) + s;                // out row = b*S+s
    }
    *(float4*)&out[orow * DMODEL + tid * 4] = o;
}

// ---------------- tf32 tensor-core GEMM, 4-stage cp.async ---------------------
// C[M,N] = A[M,K] @ W[N,K]^T, rna tf32 conversion on fragments.
// EPI: 0 = +bias ; 1 = +bias,gelu ; 2 = +bias,+res[m*1024+n] ;
//      3 = +bias,+res[m*1024+n], transposed write out[(s*B+b)*D + n]
// Dynamic smem: 4 stages x (sA 128x20 + sB 128x20) u32 = 81920 bytes.
#define TG_STAGE 2560                 // u32 per array per stage (128*20)
#define TG_BOFF  10240                // sB base offset in u32
template <int EPI>
__global__ void __launch_bounds__(256, 2)
tgemm_kernel(const float* __restrict__ A, const float* __restrict__ W,
             const float* __restrict__ bias, const float* __restrict__ res,
             float* __restrict__ C, int M, int N, int K) {
    extern __shared__ uint32_t tsm[];
    int tid = threadIdx.x;
    int m0 = blockIdx.y * 128, n0 = blockIdx.x * 128;
    int warp = tid >> 5, lane = tid & 31;
    int wm = (warp & 1) * 64, wn = (warp >> 1) * 32;
    int r = lane >> 2, cq = lane & 3;

    int ar0 = tid >> 2, ak0 = (tid & 3) * 4;
    int ar1 = ar0 + 64;
    const float* Ag0 = A + (size_t)(m0 + ar0) * K + ak0;
    const float* Ag1 = A + (size_t)(m0 + ar1) * K + ak0;
    const float* Wg0 = W + (size_t)(n0 + ar0) * K + ak0;
    const float* Wg1 = W + (size_t)(n0 + ar1) * K + ak0;
    uint32_t sbase = (uint32_t)__cvta_generic_to_shared(tsm);
    uint32_t oa0 = sbase + (ar0 * 20 + ak0) * 4;
    uint32_t oa1 = sbase + (ar1 * 20 + ak0) * 4;
    uint32_t ob0 = sbase + (TG_BOFF + ar0 * 20 + ak0) * 4;
    uint32_t ob1 = sbase + (TG_BOFF + ar1 * 20 + ak0) * 4;

    float acc[4][4][4] = {};
    int T = K >> 4;

    #define TG_PF(g) do {                                   \
        int st_ = (g) & 3; int kof_ = (g) << 4;             \
        uint32_t sof_ = st_ * (TG_STAGE * 4);               \
        cpa16(oa0 + sof_, Ag0 + kof_);                      \
        cpa16(oa1 + sof_, Ag1 + kof_);                      \
        cpa16(ob0 + sof_, Wg0 + kof_);                      \
        cpa16(ob1 + sof_, Wg1 + kof_);                      \
        cpa_commit();                                       \
    } while (0)

    TG_PF(0); TG_PF(1); TG_PF(2);      // K >= 48 always here

    for (int t = 0; t < T; t++) {
        int rem = T - 1 - t;
        if (rem >= 2) cpa_wait<2>();
        else if (rem == 1) cpa_wait<1>();
        else cpa_wait<0>();
        __syncthreads();
        const uint32_t* pA = tsm + (t & 3) * TG_STAGE;
        const uint32_t* pB = tsm + TG_BOFF + (t & 3) * TG_STAGE;
        #pragma unroll
        for (int kk = 0; kk < 16; kk += 8) {
            uint32_t af[4][4], bf[4][2];
            #pragma unroll
            for (int i = 0; i < 4; i++) {
                int mi = wm + i * 16 + r;
                af[i][0] = f2tf(__uint_as_float(pA[mi * 20 + kk + cq]));
                af[i][1] = f2tf(__uint_as_float(pA[(mi + 8) * 20 + kk + cq]));
                af[i][2] = f2tf(__uint_as_float(pA[mi * 20 + kk + cq + 4]));
                af[i][3] = f2tf(__uint_as_float(pA[(mi + 8) * 20 + kk + cq + 4]));
            }
            #pragma unroll
            for (int j = 0; j < 4; j++) {
                int nj = wn + j * 8 + r;
                bf[j][0] = f2tf(__uint_as_float(pB[nj * 20 + kk + cq]));
                bf[j][1] = f2tf(__uint_as_float(pB[nj * 20 + kk + cq + 4]));
            }
            #pragma unroll
            for (int i = 0; i < 4; i++)
                #pragma unroll
                for (int j = 0; j < 4; j++)
                    mma8(acc[i][j], af[i], bf[j]);
        }
        if (t + 3 < T) TG_PF(t + 3);
    }
    // epilogue
    float2 bb[4];
    #pragma unroll
    for (int j = 0; j < 4; j++)
        bb[j] = *(const float2*)&bias[n0 + wn + j * 8 + 2 * cq];
    #pragma unroll
    for (int i = 0; i < 4; i++)
        #pragma unroll
        for (int ph = 0; ph < 2; ph++) {
            int m = m0 + wm + i * 16 + r + ph * 8;
            #pragma unroll
            for (int j = 0; j < 4; j++) {
                int col = n0 + wn + j * 8 + 2 * cq;
                float v0 = acc[i][j][ph * 2 + 0] + bb[j].x;
                float v1 = acc[i][j][ph * 2 + 1] + bb[j].y;
                if (EPI == 1) { v0 = gelu_f(v0); v1 = gelu_f(v1); }
                if (EPI == 2 || EPI == 3) {
                    float2 rr = *(const float2*)&res[(size_t)m * 1024 + col];
                    v0 += rr.x; v1 += rr.y;
                }
                size_t ob;
                if (EPI == 3) {
                    int b = m >> 10, s = m & 1023;
                    ob = ((size_t)(s * BATCH + b)) * DMODEL + col;
                } else {
                    ob = (size_t)m * N + col;
                }
                *(float2*)&C[ob] = make_float2(v0, v1);
            }
        }
}

// ---------------- qrel: qrel[bh,q,r] = q_head[q,:] . rel_k[r,:] ---------------
__global__ void __launch_bounds__(256)
qrel_kernel(const float* __restrict__ q, const float* __restrict__ relk,
            float* __restrict__ qrel) {
    __shared__ float sR[NREL][65];
    __shared__ float sQ[64][65];
    int bh = blockIdx.y;
    int b = bh >> 4, h = bh & 15;
    int q0 = blockIdx.x * 64;
    int tid = threadIdx.x;
    const float* Q = q + ((size_t)(b * S_LEN) + q0) * DMODEL + h * HDIM;
    for (int i = tid; i < NREL * 64; i += 256) {
        int r = i >> 6, d = i & 63;
        sR[r][d] = relk[i];
    }
    for (int i = tid; i < 64 * 64; i += 256) {
        int r = i >> 6, d = i & 63;
        sQ[r][d] = Q[(size_t)r * DMODEL + d];
    }
    __syncthreads();
    for (int i = tid; i < 64 * NREL; i += 256) {
        int qq = i / NREL, r = i % NREL;
        float s = 0.f;
        #pragma unroll
        for (int d = 0; d < 64; d++) s += sQ[qq][d] * sR[r][d];
        qrel[((size_t)bh * 1024 + q0 + qq) * NREL + r] = s;
    }
}

// ---------------- fused flash attention with relative positions ---------------
// One block = (bh, 128-row q tile). 8 warps, each owns 16 q rows.
// Online softmax over 16 k-tiles of 64. Per tile: S = (QK^T + qrel)/8 via tf32
// mma, running max/sum, band rel_v contribution folded into O fragments,
// right-sum R tracked online; L = l - R - band_sum at the end.
// Dynamic smem (u32 units):
//   sQ    [128][68]   @ 0       (tf32)
//   sP    [128][68]   @ 8704    (raw fp32 p_tilde)
//   sK    [2][64][68] @ 17408   (raw fp32)
//   sV    [2][64][72] @ 26112   (raw fp32)
//   sQrel [128][104]  @ 35328   (fp32)
//   sRelv [101][68]   @ 48640   (fp32)
#define FO_Q    0
#define FO_P    8704
#define FO_K    17408
#define FO_V    26112
#define FO_QREL 35328
#define FO_RELV 48640
#define FO_END  55508          // * 4 = 222032 bytes

__global__ void __launch_bounds__(256, 1)
flash_kernel(const float* __restrict__ q, const float* __restrict__ k,
             const float* __restrict__ v, const float* __restrict__ qrel,
             const float* __restrict__ relv, float* __restrict__ o) {
    extern __shared__ uint32_t fsm[];
    uint32_t* sQ = fsm + FO_Q;
    uint32_t* sP = fsm + FO_P;
    float* sQrel = (float*)(fsm + FO_QREL);
    float* sRelv = (float*)(fsm + FO_RELV);
    int bh = blockIdx.y;
    int b = bh >> 4, h = bh & 15;
    int q0 = blockIdx.x * 128;
    int tid = threadIdx.x, warp = tid >> 5, lane = tid & 31;
    int r = lane >> 2, cq = lane & 3;
    int wq = warp * 16;                      // warp's local q base

    const float* Qg = q + ((size_t)(b << 10) + q0) * 1024 + h * 64;
    const float* Kg = k + ((size_t)(b << 10)) * 1024 + h * 64;
    const float* Vg = v + ((size_t)(b << 10)) * 1024 + h * 64;
    uint32_t sbase = (uint32_t)__cvta_generic_to_shared(fsm);

    // coop loads: Q tile (tf32), qrel tile, rel_v table
    for (int i = tid; i < 2048; i += 256) {              // 128 rows x 16 f4
        int row = i >> 4, cg = (i & 15) * 4;
        float4 t = *(const float4*)&Qg[(size_t)row * 1024 + cg];
        sQ[row * 68 + cg + 0] = f2tf(t.x);
        sQ[row * 68 + cg + 1] = f2tf(t.y);
        sQ[row * 68 + cg + 2] = f2tf(t.z);
        sQ[row * 68 + cg + 3] = f2tf(t.w);
    }
    {
        const float* QR = qrel + ((size_t)bh * 1024 + q0) * NREL;
        for (int i = tid; i < 128 * NREL; i += 256)
            sQrel[(i / NREL) * 104 + (i % NREL)] = QR[i];
        for (int i = tid; i < NREL * 64; i += 256)
            sRelv[(i >> 6) * 68 + (i & 63)] = relv[i];
    }

    // K/V tile prefetch: 1024 16B-chunks per array; 4 per thread per array
    #define FL_PF(kt) do {                                                   \
        int buf_ = (kt) & 1;                                                 \
        uint32_t kb_ = sbase + (FO_K + buf_ * 4352) * 4;                     \
        uint32_t vb_ = sbase + (FO_V + buf_ * 4608) * 4;                     \
        const float* Ks_ = Kg + (size_t)((kt) * 64) * 1024;                  \
        const float* Vs_ = Vg + (size_t)((kt) * 64) * 1024;                  \
        _Pragma("unroll")                                                    \
        for (int i_ = 0; i_ < 4; i_++) {                                     \
            int c_ = tid + 256 * i_;                                         \
            int row_ = c_ >> 4, cg_ = (c_ & 15) * 4;                         \
            cpa16(kb_ + (row_ * 68 + cg_) * 4, Ks_ + (size_t)row_ * 1024 + cg_); \
            cpa16(vb_ + (row_ * 72 + cg_) * 4, Vs_ + (size_t)row_ * 1024 + cg_); \
        }                                                                    \
        cpa_commit();                                                        \
    } while (0)

    FL_PF(0);

    float m0_ = -1e30f, m1_ = -1e30f;
    float l0 = 0.f, l1 = 0.f, R0 = 0.f, R1 = 0.f, bs0 = 0.f, bs1 = 0.f;
    float O[8][4] = {};

    for (int kt = 0; kt < 16; kt++) {
        cpa_wait<0>();
        __syncthreads();
        if (kt + 1 < 16) FL_PF(kt + 1);
        const uint32_t* sKc = fsm + FO_K + (kt & 1) * 4352;
        const uint32_t* sVc = fsm + FO_V + (kt & 1) * 4608;
        int k0g = kt * 64;

        // ---- S = Q @ K^T ----
        float sc[8][4] = {};
        #pragma unroll
        for (int kk = 0; kk < 64; kk += 8) {
            uint32_t af[4];
            af[0] = sQ[(wq + r) * 68 + kk + cq];
            af[1] = sQ[(wq + r + 8) * 68 + kk + cq];
            af[2] = sQ[(wq + r) * 68 + kk + cq + 4];
            af[3] = sQ[(wq + r + 8) * 68 + kk + cq + 4];
            #pragma unroll
            for (int j = 0; j < 8; j++) {
                uint32_t bf[2];
                bf[0] = sKc[(8 * j + r) * 68 + kk + cq];
                bf[1] = sKc[(8 * j + r) * 68 + kk + cq + 4];
                mma8(sc[j], af, bf);
            }
        }
        // ---- bias + scale ----
        int row0 = q0 + wq + r, row1 = row0 + 8;
        #pragma unroll
        for (int j = 0; j < 8; j++) {
            #pragma unroll
            for (int e = 0; e < 4; e++) {
                int row_abs = (e < 2) ? row0 : row1;
                int rowl = (e < 2) ? (wq + r) : (wq + r + 8);
                int col_abs = k0g + 8 * j + 2 * cq + (e & 1);
                int d = min(max(col_abs - row_abs, -50), 50) + 50;
                sc[j][e] = (sc[j][e] + sQrel[rowl * 104 + d]) * 0.125f;
            }
        }
        // ---- online softmax stats ----
        float tm0 = -1e30f, tm1 = -1e30f;
        #pragma unroll
        for (int j = 0; j < 8; j++) {
            tm0 = fmaxf(tm0, fmaxf(sc[j][0], sc[j][1]));
            tm1 = fmaxf(tm1, fmaxf(sc[j][2], sc[j][3]));
        }
        tm0 = fmaxf(tm0, __shfl_xor_sync(0xffffffffu, tm0, 1));
        tm0 = fmaxf(tm0, __shfl_xor_sync(0xffffffffu, tm0, 2));
        tm1 = fmaxf(tm1, __shfl_xor_sync(0xffffffffu, tm1, 1));
        tm1 = fmaxf(tm1, __shfl_xor_sync(0xffffffffu, tm1, 2));
        float mn0 = fmaxf(m0_, tm0), mn1 = fmaxf(m1_, tm1);
        float a0 = __expf(m0_ - mn0), a1 = __expf(m1_ - mn1);
        m0_ = mn0; m1_ = mn1;
        float ls0 = 0.f, ls1 = 0.f, rs0 = 0.f, rs1 = 0.f;
        #pragma unroll
        for (int j = 0; j < 8; j++) {
            #pragma unroll
            for (int e = 0; e < 4; e++) {
                int row_abs = (e < 2) ? row0 : row1;
                int col_abs = k0g + 8 * j + 2 * cq + (e & 1);
                float p = __expf(sc[j][e] - ((e < 2) ? mn0 : mn1));
                sc[j][e] = p;
                if (e < 2) { ls0 += p; if (col_abs - row_abs >= 50) rs0 += p; }
                else       { ls1 += p; if (col_abs - row_abs >= 50) rs1 += p; }
            }
        }
        l0 = l0 * a0 + ls0; l1 = l1 * a1 + ls1;
        R0 = R0 * a0 + rs0; R1 = R1 * a1 + rs1;
        bs0 *= a0; bs1 *= a1;
        #pragma unroll
        for (int j = 0; j < 8; j++) {
            O[j][0] *= a0; O[j][1] *= a0; O[j][2] *= a1; O[j][3] *= a1;
        }
        // ---- write p to sP (raw fp32 bits; mma truncates to tf32) ----
        #pragma unroll
        for (int j = 0; j < 8; j++) {
            sP[(wq + r) * 68 + 8 * j + 2 * cq]     = __float_as_uint(sc[j][0]);
            sP[(wq + r) * 68 + 8 * j + 2 * cq + 1] = __float_as_uint(sc[j][1]);
            sP[(wq + r + 8) * 68 + 8 * j + 2 * cq]     = __float_as_uint(sc[j][2]);
            sP[(wq + r + 8) * 68 + 8 * j + 2 * cq + 1] = __float_as_uint(sc[j][3]);
        }
        __syncwarp();
        // ---- near-diagonal band: O += p * rel_v[k-q+50] ----
        if (k0g <= q0 + wq + 15 + 49 && k0g + 63 >= q0 + wq - 49) {
            #pragma unroll
            for (int ph = 0; ph < 2; ph++) {
                int rowl = wq + r + ph * 8;
                int base = (q0 + rowl) - k0g;       // kloc where k == q
                int klo = max(0, base - 49), khi = min(63, base + 49);
                float bsl = 0.f;
                for (int kl = klo; kl <= khi; kl++) {
                    float pv = __uint_as_float(sP[rowl * 68 + kl]);
                    const float* rv = &sRelv[(kl - base + 50) * 68];
                    bsl += pv;
                    #pragma unroll
                    for (int j = 0; j < 8; j++) {
                        int c0 = 8 * j + 2 * cq;
                        O[j][ph * 2 + 0] += pv * rv[c0];
                        O[j][ph * 2 + 1] += pv * rv[c0 + 1];
                    }
                }
                if (ph == 0) bs0 += bsl; else bs1 += bsl;
            }
        }
        // ---- O += P @ V ----
        #pragma unroll
        for (int kk = 0; kk < 64; kk += 8) {
            uint32_t af[4];
            af[0] = sP[(wq + r) * 68 + kk + cq];
            af[1] = sP[(wq + r + 8) * 68 + kk + cq];
            af[2] = sP[(wq + r) * 68 + kk + cq + 4];
            af[3] = sP[(wq + r + 8) * 68 + kk + cq + 4];
            #pragma unroll
            for (int j = 0; j < 8; j++) {
                uint32_t bf[2];
                bf[0] = sVc[(kk + cq) * 72 + 8 * j + r];
                bf[1] = sVc[(kk + cq + 4) * 72 + 8 * j + r];
                mma8(O[j], af, bf);
            }
        }
    }
    // ---- finalize ----
    l0 += __shfl_xor_sync(0xffffffffu, l0, 1);
    l0 += __shfl_xor_sync(0xffffffffu, l0, 2);
    l1 += __shfl_xor_sync(0xffffffffu, l1, 1);
    l1 += __shfl_xor_sync(0xffffffffu, l1, 2);
    R0 += __shfl_xor_sync(0xffffffffu, R0, 1);
    R0 += __shfl_xor_sync(0xffffffffu, R0, 2);
    R1 += __shfl_xor_sync(0xffffffffu, R1, 1);
    R1 += __shfl_xor_sync(0xffffffffu, R1, 2);
    float L0 = l0 - R0 - bs0, L1 = l1 - R1 - bs1;
    float inv0 = 1.0f / l0, inv1 = 1.0f / l1;
    int rowA = q0 + wq + r, rowB = rowA + 8;
    float* oA = o + ((size_t)(b << 10) + rowA) * 1024 + h * 64;
    float* oB = o + ((size_t)(b << 10) + rowB) * 1024 + h * 64;
    #pragma unroll
    for (int j = 0; j < 8; j++) {
        int c0 = 8 * j + 2 * cq;
        float rv0a = sRelv[c0], rv0b = sRelv[c0 + 1];
        float rva = sRelv[100 * 68 + c0], rvb = sRelv[100 * 68 + c0 + 1];
        *(float2*)&oA[c0] = make_float2(
            (O[j][0] + L0 * rv0a + R0 * rva) * inv0,
            (O[j][1] + L0 * rv0b + R0 * rvb) * inv0);
        *(float2*)&oB[c0] = make_float2(
            (O[j][2] + L1 * rv0a + R1 * rva) * inv1,
            (O[j][3] + L1 * rv0b + R1 * rvb) * inv1);
    }
}

// ---------------- host launch -------------------------------------------------
extern "C" void kernel_launch(void* const* d_in, const int* in_sizes, int n_in,
                              void* d_out, int out_size) {
    const float* x     = (const float*)d_in[0];
    const float* Wq    = (const float*)d_in[1];
    const float* bq    = (const float*)d_in[2];
    const float* Wk    = (const float*)d_in[3];
    const float* bk    = (const float*)d_in[4];
    const float* Wv    = (const float*)d_in[5];
    const float* bv    = (const float*)d_in[6];
    const float* Wo    = (const float*)d_in[7];
    const float* bo    = (const float*)d_in[8];
    const float* rel_k = (const float*)d_in[9];
    const float* rel_v = (const float*)d_in[10];
    const float* ga    = (const float*)d_in[11];
    const float* gf    = (const float*)d_in[12];
    const float* W_in  = (const float*)d_in[13];
    const float* b_in  = (const float*)d_in[14];
    const float* W_out = (const float*)d_in[15];
    const float* b_out = (const float*)d_in[16];
    float* out = (float*)d_out;

    float *hn, *qb, *kb, *vb, *qr, *ob, *h2, *ffin, *gel;
    cudaGetSymbolAddress((void**)&hn,   g_hn);
    cudaGetSymbolAddress((void**)&qb,   g_q);
    cudaGetSymbolAddress((void**)&kb,   g_k);
    cudaGetSymbolAddress((void**)&vb,   g_v);
    cudaGetSymbolAddress((void**)&qr,   g_qrel);
    cudaGetSymbolAddress((void**)&ob,   g_o);
    cudaGetSymbolAddress((void**)&h2,   g_h2);
    cudaGetSymbolAddress((void**)&ffin, g_ffin);
    cudaGetSymbolAddress((void**)&gel,  g_gelu);

    const int TG_SMEM = 20480 * 4;                 // 81920 B
    const int FL_SMEM = FO_END * 4;                // 222032 B
    cudaFuncSetAttribute(tgemm_kernel<0>, cudaFuncAttributeMaxDynamicSharedMemorySize, TG_SMEM);
    cudaFuncSetAttribute(tgemm_kernel<1>, cudaFuncAttributeMaxDynamicSharedMemorySize, TG_SMEM);
    cudaFuncSetAttribute(tgemm_kernel<2>, cudaFuncAttributeMaxDynamicSharedMemorySize, TG_SMEM);
    cudaFuncSetAttribute(tgemm_kernel<3>, cudaFuncAttributeMaxDynamicSharedMemorySize, TG_SMEM);
    cudaFuncSetAttribute(flash_kernel, cudaFuncAttributeMaxDynamicSharedMemorySize, FL_SMEM);

    // 1. h = rmsnorm(x, g_attn), transpose [S,B,D] -> [B,S,D]
    rmsnorm_kernel<<<M4, 256>>>(x, ga, hn, 1);
    // 2. q, k, v
    dim3 g1(DMODEL / 128, M4 / 128);
    tgemm_kernel<0><<<g1, 256, TG_SMEM>>>(hn, Wq, bq, nullptr, qb, M4, DMODEL, DMODEL);
    tgemm_kernel<0><<<g1, 256, TG_SMEM>>>(hn, Wk, bk, nullptr, kb, M4, DMODEL, DMODEL);
    tgemm_kernel<0><<<g1, 256, TG_SMEM>>>(hn, Wv, bv, nullptr, vb, M4, DMODEL, DMODEL);
    // 3. qrel
    qrel_kernel<<<dim3(16, 64), 256>>>(qb, rel_k, qr);
    // 4. fused flash attention (scores + softmax + rel terms + AV)
    flash_kernel<<<dim3(8, 64), 256, FL_SMEM>>>(qb, kb, vb, qr, rel_v, ob);
    // 5. h2 = hn + o @ Wo^T + bo
    tgemm_kernel<2><<<g1, 256, TG_SMEM>>>(ob, Wo, bo, hn, h2, M4, DMODEL, DMODEL);
    // 6. ffin = rmsnorm(h2, g_ff)
    rmsnorm_kernel<<<M4, 256>>>(h2, gf, ffin, 0);
    // 7. gelu(ffin @ W_in^T + b_in)
    tgemm_kernel<1><<<dim3(DFF / 128, M4 / 128), 256, TG_SMEM>>>(ffin, W_in, b_in, nullptr,
                                                                 gel, M4, DFF, DMODEL);
    // 8. out = h2 + gel @ W_out^T + b_out  (written back in [S,B,D] order)
    tgemm_kernel<3><<<g1, 256, TG_SMEM>>>(gel, W_out, b_out, h2, out, M4, DMODEL, DFF);
}